// round 1
// baseline (speedup 1.0000x reference)
#include <cuda_runtime.h>
#include <math.h>

#define BH   64
#define S    4096
#define D    64
#define LOGN 12
#define NT   512

// Static scratch (allocation-free rule: __device__ globals)
__device__ float2 g_x[(size_t)BH * D * S];   // packed q + i*k, layout [bh][d][s]  (134 MB)
__device__ float  g_w[(size_t)BH * D * S];   // sorted softmax weights [bh][d][i]  (67 MB)

// ---------------- transpose + pack:  [bh][s][d] -> [bh][d][s] as (q, k) float2 ----------------
__global__ void transpose_pack(const float* __restrict__ q, const float* __restrict__ k) {
    __shared__ float qt[32][33];
    __shared__ float kt[32][33];
    int bh = blockIdx.z;
    int s0 = blockIdx.x * 32;
    int d0 = blockIdx.y * 32;
    int tx = threadIdx.x, ty = threadIdx.y;
    const float* qb = q + (size_t)bh * S * D;
    const float* kb = k + (size_t)bh * S * D;
#pragma unroll
    for (int r = 0; r < 4; r++) {
        int s = s0 + ty + r * 8;
        qt[ty + r * 8][tx] = qb[(size_t)s * D + d0 + tx];
        kt[ty + r * 8][tx] = kb[(size_t)s * D + d0 + tx];
    }
    __syncthreads();
#pragma unroll
    for (int r = 0; r < 4; r++) {
        int d = d0 + ty + r * 8;
        int s = s0 + tx;
        g_x[((size_t)bh * D + d) * S + s] = make_float2(qt[tx][ty + r * 8], kt[tx][ty + r * 8]);
    }
}

// ---------------- per-series: FFT -> cross-spectrum -> IFFT -> sort desc -> softmax ----------------
__global__ __launch_bounds__(NT) void fft_corr_sort() {
    __shared__ float2 sx[S];        // 32 KB
    __shared__ float2 tw[S / 2];    // 16 KB ; reused as reduction buffer at the end
    int tid = threadIdx.x;
    int idx = blockIdx.x;           // bh*64 + d
    const float2* gx = g_x + (size_t)idx * S;

    // twiddle table tw[k] = exp(-2*pi*i*k/S), precise via sincospif
    for (int k = tid; k < S / 2; k += NT) {
        float sn, cs;
        sincospif(-2.0f * (float)k / (float)S, &sn, &cs);
        tw[k] = make_float2(cs, sn);
    }
    for (int j = tid; j < S; j += NT) sx[j] = gx[j];
    __syncthreads();

    // forward radix-2 DIF (natural in -> bit-reversed out)
#pragma unroll 1
    for (int st = 0; st < LOGN; st++) {
        int half = S >> (st + 1);
#pragma unroll
        for (int p = 0; p < (S / 2) / NT; p++) {
            int w   = tid + p * NT;
            int pos = w & (half - 1);
            int grp = w >> (LOGN - 1 - st);
            int i0  = (grp << (LOGN - st)) + pos;
            int i1  = i0 + half;
            float2 a = sx[i0], b = sx[i1];
            float2 t  = make_float2(a.x - b.x, a.y - b.y);
            float2 wv = tw[pos << st];
            sx[i0] = make_float2(a.x + b.x, a.y + b.y);
            sx[i1] = make_float2(t.x * wv.x - t.y * wv.y, t.x * wv.y + t.y * wv.x);
        }
        __syncthreads();
    }

    // cross-spectrum P[f] = Q[f]*conj(K[f]) with q+ik unpack, in bit-reversed positions.
    // Pairs (f, S-f) are disjoint and handled by one thread each -> no intra-step sync needed.
    for (int f = tid; f <= S / 2; f += NT) {
        int fp = (S - f) & (S - 1);
        int j  = __brev(f)  >> (32 - LOGN);
        int jp = __brev(fp) >> (32 - LOGN);
        float2 X = sx[j], Xp = sx[jp];
        float Qr = 0.5f * (X.x + Xp.x);
        float Qi = 0.5f * (X.y - Xp.y);
        float Kr = 0.5f * (X.y + Xp.y);
        float Ki = 0.5f * (Xp.x - X.x);
        float Pr = Qr * Kr + Qi * Ki;
        float Pi = Qi * Kr - Qr * Ki;
        sx[j]  = make_float2(Pr, Pi);
        sx[jp] = make_float2(Pr, -Pi);
    }
    __syncthreads();

    // inverse radix-2 DIT (bit-reversed in -> natural out), conj twiddles
#pragma unroll 1
    for (int st = 0; st < LOGN; st++) {
        int half = 1 << st;
#pragma unroll
        for (int p = 0; p < (S / 2) / NT; p++) {
            int w   = tid + p * NT;
            int pos = w & (half - 1);
            int grp = w >> st;
            int i0  = (grp << (st + 1)) + pos;
            int i1  = i0 + half;
            float2 a = sx[i0], b = sx[i1];
            float2 wv = tw[pos << (LOGN - 1 - st)];  // use conj(wv)
            float2 bw = make_float2(b.x * wv.x + b.y * wv.y, b.y * wv.x - b.x * wv.y);
            sx[i0] = make_float2(a.x + bw.x, a.y + bw.y);
            sx[i1] = make_float2(a.x - bw.x, a.y - bw.y);
        }
        __syncthreads();
    }

    // extract corr = Re/N, repack smem as float[4096]
    const float invN = 1.0f / (float)S;
    float r[S / NT];
#pragma unroll
    for (int p = 0; p < S / NT; p++) r[p] = sx[tid + p * NT].x * invN;
    __syncthreads();
    float* vals = (float*)sx;
#pragma unroll
    for (int p = 0; p < S / NT; p++) vals[tid + p * NT] = r[p];
    __syncthreads();

    // bitonic sort, descending
    for (int k2 = 2; k2 <= S; k2 <<= 1) {
        for (int j2 = k2 >> 1; j2 > 0; j2 >>= 1) {
#pragma unroll
            for (int p = 0; p < (S / 2) / NT; p++) {
                int w  = tid + p * NT;
                int i  = ((w & ~(j2 - 1)) << 1) | (w & (j2 - 1));
                int ip = i | j2;
                float a = vals[i], b = vals[ip];
                bool desc = ((i & k2) == 0);
                if (desc ? (a < b) : (a > b)) { vals[i] = b; vals[ip] = a; }
            }
            __syncthreads();
        }
    }

    // softmax over sorted axis (max = vals[0]), write weights coalesced
    float m = vals[0];
    __syncthreads();
    float* red = (float*)tw;
    float ev[S / NT];
    float partial = 0.f;
#pragma unroll
    for (int p = 0; p < S / NT; p++) {
        float e = __expf(vals[tid + p * NT] - m);
        ev[p] = e;
        partial += e;
    }
    red[tid] = partial;
    __syncthreads();
    for (int sct = NT / 2; sct > 0; sct >>= 1) {
        if (tid < sct) red[tid] += red[tid + sct];
        __syncthreads();
    }
    float invZ = 1.0f / red[0];
    float* gw = g_w + (size_t)idx * S;
#pragma unroll
    for (int p = 0; p < S / NT; p++) gw[tid + p * NT] = ev[p] * invZ;
}

// ---------------- out[bh,i,l] = sum_j W[bh,j,i] * V[bh,j,l]   (j,l in [0,64), i in [0,4096)) ----------------
__global__ __launch_bounds__(256) void wgemm(const float* __restrict__ v, float* __restrict__ out) {
    __shared__ float Vs[D * D];        // 16 KB
    __shared__ float Ws[D][128];       // 32 KB
    int bh  = blockIdx.y;
    int i0  = blockIdx.x * 128;
    int tid = threadIdx.x;
    const float* vb = v + (size_t)bh * S * D;   // first D seq rows
#pragma unroll
    for (int p = 0; p < (D * D) / 256; p++) Vs[tid + p * 256] = vb[tid + p * 256];
    const float* wb = g_w + (size_t)bh * D * S + i0;
#pragma unroll
    for (int p = 0; p < (D * 128) / 256; p++) {
        int q = tid + p * 256;
        int j = q >> 7, i = q & 127;
        Ws[j][i] = wb[(size_t)j * S + i];
    }
    __syncthreads();
    int il = tid & 15, ir = tid >> 4;   // l-tile of 4, i-tile of 8
    float acc[8][4];
#pragma unroll
    for (int a = 0; a < 8; a++)
#pragma unroll
        for (int b = 0; b < 4; b++) acc[a][b] = 0.f;
#pragma unroll 4
    for (int j = 0; j < D; j++) {
        float4 vl = *(const float4*)&Vs[j * D + il * 4];
#pragma unroll
        for (int a = 0; a < 8; a++) {
            float wv = Ws[j][ir * 8 + a];
            acc[a][0] += wv * vl.x;
            acc[a][1] += wv * vl.y;
            acc[a][2] += wv * vl.z;
            acc[a][3] += wv * vl.w;
        }
    }
    float* ob = out + ((size_t)bh * S + i0) * D;
#pragma unroll
    for (int a = 0; a < 8; a++) {
        float4 o = make_float4(acc[a][0], acc[a][1], acc[a][2], acc[a][3]);
        *(float4*)&ob[(size_t)(ir * 8 + a) * D + il * 4] = o;
    }
}

extern "C" void kernel_launch(void* const* d_in, const int* in_sizes, int n_in,
                              void* d_out, int out_size) {
    const float* q = (const float*)d_in[0];
    const float* k = (const float*)d_in[1];
    const float* v = (const float*)d_in[2];
    float* out = (float*)d_out;

    dim3 tb(32, 8);
    dim3 tg(S / 32, D / 32, BH);
    transpose_pack<<<tg, tb>>>(q, k);

    fft_corr_sort<<<BH * D, NT>>>();

    dim3 gg(S / 128, BH);
    wgemm<<<gg, 256>>>(v, out);
}

// round 2
// speedup vs baseline: 1.2667x; 1.2667x over previous
#include <cuda_runtime.h>
#include <math.h>

#define BH   64
#define S    4096
#define D    64
#define NT   512
#define SIDX(a) ((a) + ((a) >> 3))

// Static scratch (allocation-free rule: __device__ globals)
__device__ float2 g_x[(size_t)BH * D * S];   // packed q + i*k, layout [bh][d][s]
__device__ float  g_w[(size_t)BH * D * S];   // sorted softmax weights [bh][d][i]

// ---------------- complex helpers ----------------
__device__ __forceinline__ float2 cadd(float2 a, float2 b){ return make_float2(a.x+b.x, a.y+b.y); }
__device__ __forceinline__ float2 csub(float2 a, float2 b){ return make_float2(a.x-b.x, a.y-b.y); }
__device__ __forceinline__ float2 cmul(float2 a, float2 b){ return make_float2(a.x*b.x - a.y*b.y, a.x*b.y + a.y*b.x); }
__device__ __forceinline__ float2 cconj(float2 a){ return make_float2(a.x, -a.y); }

// octal-digit reversal of 12-bit index
__device__ __forceinline__ int rev8(int f) {
    return ((f & 7) << 9) | (((f >> 3) & 7) << 6) | (((f >> 6) & 7) << 3) | ((f >> 9) & 7);
}

// 8-point DFT in registers, natural-order outputs. SGN=-1 forward, +1 inverse.
template<int SGN>
__device__ __forceinline__ void dft8(float2 v[8]) {
    const float c = 0.70710678118654752f;
    float2 a0 = cadd(v[0], v[4]), a4 = csub(v[0], v[4]);
    float2 a1 = cadd(v[1], v[5]), a5 = csub(v[1], v[5]);
    float2 a2 = cadd(v[2], v[6]), a6 = csub(v[2], v[6]);
    float2 a3 = cadd(v[3], v[7]), a7 = csub(v[3], v[7]);
    a5 = cmul(a5, make_float2(c, SGN * c));
    a6 = (SGN < 0) ? make_float2(a6.y, -a6.x) : make_float2(-a6.y, a6.x);
    a7 = cmul(a7, make_float2(-c, SGN * c));
    // even group -> Y0,Y4,Y2,Y6
    float2 b0 = cadd(a0, a2), b2 = csub(a0, a2);
    float2 b1 = cadd(a1, a3), b3 = csub(a1, a3);
    b3 = (SGN < 0) ? make_float2(b3.y, -b3.x) : make_float2(-b3.y, b3.x);
    float2 e0 = cadd(b0, b1), e1 = csub(b0, b1);
    float2 e2 = cadd(b2, b3), e3 = csub(b2, b3);
    // odd group -> Y1,Y5,Y3,Y7
    float2 d0 = cadd(a4, a6), d2 = csub(a4, a6);
    float2 d1 = cadd(a5, a7), d3 = csub(a5, a7);
    d3 = (SGN < 0) ? make_float2(d3.y, -d3.x) : make_float2(-d3.y, d3.x);
    float2 o0 = cadd(d0, d1), o1 = csub(d0, d1);
    float2 o2 = cadd(d2, d3), o3 = csub(d2, d3);
    v[0] = e0; v[4] = e1; v[2] = e2; v[6] = e3;
    v[1] = o0; v[5] = o1; v[3] = o2; v[7] = o3;
}

// ---------------- transpose + pack:  [bh][s][d] -> [bh][d][s] as (q, k) float2 ----------------
__global__ void transpose_pack(const float* __restrict__ q, const float* __restrict__ k) {
    __shared__ float qt[32][33];
    __shared__ float kt[32][33];
    int bh = blockIdx.z;
    int s0 = blockIdx.x * 32;
    int d0 = blockIdx.y * 32;
    int tx = threadIdx.x, ty = threadIdx.y;
    const float* qb = q + (size_t)bh * S * D;
    const float* kb = k + (size_t)bh * S * D;
#pragma unroll
    for (int r = 0; r < 4; r++) {
        int s = s0 + ty + r * 8;
        qt[ty + r * 8][tx] = qb[(size_t)s * D + d0 + tx];
        kt[ty + r * 8][tx] = kb[(size_t)s * D + d0 + tx];
    }
    __syncthreads();
#pragma unroll
    for (int r = 0; r < 4; r++) {
        int d = d0 + ty + r * 8;
        int s = s0 + tx;
        g_x[((size_t)bh * D + d) * S + s] = make_float2(qt[tx][ty + r * 8], kt[tx][ty + r * 8]);
    }
}

// ---------------- per-series: radix-8 FFT -> cross-spectrum -> IFFT -> hybrid bitonic sort -> softmax ----------------
__global__ __launch_bounds__(NT, 2) void fft_corr_sort() {
    __shared__ float  s_re[SIDX(S)];   // 18 KB (padded)
    __shared__ float  s_im[SIDX(S)];   // 18 KB
    __shared__ float2 s_tw[512];       // 4 KB : W_4096^k, k=0..511
    int tid = threadIdx.x;
    const float2* gx = g_x + (size_t)blockIdx.x * S;

    // precise twiddle table
    for (int k = tid; k < 512; k += NT) {
        float sn, cs;
        sincospif(-(float)k / 2048.0f, &sn, &cs);
        s_tw[k] = make_float2(cs, sn);
    }

    float2 v[8];

    // ---- forward stage 0 : L=4096, stride 512, p=tid (load from global) ----
#pragma unroll
    for (int r = 0; r < 8; r++) v[r] = gx[tid + 512 * r];
    __syncthreads();                       // twiddle table ready
    dft8<-1>(v);
    {
        float2 w = s_tw[tid], wp = w;
#pragma unroll
        for (int r = 1; r < 8; r++) { v[r] = cmul(v[r], wp); wp = cmul(wp, w); }
#pragma unroll
        for (int r = 0; r < 8; r++) { int a = tid + 512 * r; s_re[SIDX(a)] = v[r].x; s_im[SIDX(a)] = v[r].y; }
    }
    __syncthreads();
    // ---- forward stage 1 : L=512, stride 64 ----
    {
        int base = (tid >> 6) << 9, p = tid & 63;
#pragma unroll
        for (int r = 0; r < 8; r++) { int a = base + p + 64 * r; v[r] = make_float2(s_re[SIDX(a)], s_im[SIDX(a)]); }
        dft8<-1>(v);
        float2 w = s_tw[p << 3], wp = w;
#pragma unroll
        for (int r = 1; r < 8; r++) { v[r] = cmul(v[r], wp); wp = cmul(wp, w); }
#pragma unroll
        for (int r = 0; r < 8; r++) { int a = base + p + 64 * r; s_re[SIDX(a)] = v[r].x; s_im[SIDX(a)] = v[r].y; }
    }
    __syncthreads();
    // ---- forward stage 2 : L=64, stride 8 ----
    {
        int base = (tid >> 3) << 6, p = tid & 7;
#pragma unroll
        for (int r = 0; r < 8; r++) { int a = base + p + 8 * r; v[r] = make_float2(s_re[SIDX(a)], s_im[SIDX(a)]); }
        dft8<-1>(v);
        float2 w = s_tw[p << 6], wp = w;
#pragma unroll
        for (int r = 1; r < 8; r++) { v[r] = cmul(v[r], wp); wp = cmul(wp, w); }
#pragma unroll
        for (int r = 0; r < 8; r++) { int a = base + p + 8 * r; s_re[SIDX(a)] = v[r].x; s_im[SIDX(a)] = v[r].y; }
    }
    __syncthreads();
    // ---- forward stage 3 : L=8, stride 1, no twiddle ----
    {
        int base = tid << 3;
#pragma unroll
        for (int r = 0; r < 8; r++) { int a = base + r; v[r] = make_float2(s_re[SIDX(a)], s_im[SIDX(a)]); }
        dft8<-1>(v);
#pragma unroll
        for (int r = 0; r < 8; r++) { int a = base + r; s_re[SIDX(a)] = v[r].x; s_im[SIDX(a)] = v[r].y; }
    }
    __syncthreads();

    // ---- cross-spectrum P[f] = Q[f]*conj(K[f]) in octal-digit-reversed layout ----
    for (int f = tid; f <= 2048; f += NT) {
        int fp = (S - f) & (S - 1);
        int j  = rev8(f), jp = rev8(fp);
        float2 X  = make_float2(s_re[SIDX(j)],  s_im[SIDX(j)]);
        float2 Xp = make_float2(s_re[SIDX(jp)], s_im[SIDX(jp)]);
        float Qr = 0.5f * (X.x + Xp.x);
        float Qi = 0.5f * (X.y - Xp.y);
        float Kr = 0.5f * (X.y + Xp.y);
        float Ki = 0.5f * (Xp.x - X.x);
        float Pr = Qr * Kr + Qi * Ki;
        float Pi = Qi * Kr - Qr * Ki;
        s_re[SIDX(j)]  = Pr;  s_im[SIDX(j)]  = Pi;
        s_re[SIDX(jp)] = Pr;  s_im[SIDX(jp)] = -Pi;
    }
    __syncthreads();

    // ---- inverse stage 0 : L=8, stride 1 ----
    {
        int base = tid << 3;
#pragma unroll
        for (int r = 0; r < 8; r++) { int a = base + r; v[r] = make_float2(s_re[SIDX(a)], s_im[SIDX(a)]); }
        dft8<1>(v);
#pragma unroll
        for (int r = 0; r < 8; r++) { int a = base + r; s_re[SIDX(a)] = v[r].x; s_im[SIDX(a)] = v[r].y; }
    }
    __syncthreads();
    // ---- inverse stage 1 : L=64, stride 8 ----
    {
        int base = (tid >> 3) << 6, p = tid & 7;
#pragma unroll
        for (int r = 0; r < 8; r++) { int a = base + p + 8 * r; v[r] = make_float2(s_re[SIDX(a)], s_im[SIDX(a)]); }
        float2 w = cconj(s_tw[p << 6]), wp = w;
#pragma unroll
        for (int r = 1; r < 8; r++) { v[r] = cmul(v[r], wp); wp = cmul(wp, w); }
        dft8<1>(v);
#pragma unroll
        for (int r = 0; r < 8; r++) { int a = base + p + 8 * r; s_re[SIDX(a)] = v[r].x; s_im[SIDX(a)] = v[r].y; }
    }
    __syncthreads();
    // ---- inverse stage 2 : L=512, stride 64 ----
    {
        int base = (tid >> 6) << 9, p = tid & 63;
#pragma unroll
        for (int r = 0; r < 8; r++) { int a = base + p + 64 * r; v[r] = make_float2(s_re[SIDX(a)], s_im[SIDX(a)]); }
        float2 w = cconj(s_tw[p << 3]), wp = w;
#pragma unroll
        for (int r = 1; r < 8; r++) { v[r] = cmul(v[r], wp); wp = cmul(wp, w); }
        dft8<1>(v);
#pragma unroll
        for (int r = 0; r < 8; r++) { int a = base + p + 64 * r; s_re[SIDX(a)] = v[r].x; s_im[SIDX(a)] = v[r].y; }
    }
    __syncthreads();
    // ---- inverse stage 3 : L=4096, stride 512 ; write only scaled real part ----
    {
        const float invN = 1.0f / (float)S;
#pragma unroll
        for (int r = 0; r < 8; r++) { int a = tid + 512 * r; v[r] = make_float2(s_re[SIDX(a)], s_im[SIDX(a)]); }
        float2 w = cconj(s_tw[tid]), wp = w;
#pragma unroll
        for (int r = 1; r < 8; r++) { v[r] = cmul(v[r], wp); wp = cmul(wp, w); }
        dft8<1>(v);
#pragma unroll
        for (int r = 0; r < 8; r++) { int a = tid + 512 * r; s_re[SIDX(a)] = v[r].x * invN; }
    }
    __syncthreads();

    // ---- hybrid bitonic sort, descending. Thread t owns elements [8t, 8t+8) in rv[]. ----
    float rv[8];
#pragma unroll
    for (int e = 0; e < 8; e++) rv[e] = s_re[SIDX(8 * tid + e)];

#pragma unroll 1
    for (int k2 = 2; k2 <= S; k2 <<= 1) {
        // smem passes: j2 >= 256 (cross-warp)
#pragma unroll 1
        for (int j2 = k2 >> 1; j2 >= 256; j2 >>= 1) {
#pragma unroll
            for (int e = 0; e < 8; e++) s_re[SIDX(8 * tid + e)] = rv[e];
            __syncthreads();
#pragma unroll
            for (int e = 0; e < 8; e++) {
                int i = 8 * tid + e;
                float b = s_re[SIDX(i ^ j2)];
                bool up = ((i & k2) == 0);
                bool lo = ((i & j2) == 0);
                rv[e] = (up == lo) ? fmaxf(rv[e], b) : fminf(rv[e], b);
            }
            __syncthreads();
        }
        // shfl passes: 8 <= j2 <= 128 (within-warp, no syncs)
        int jhi = (k2 >> 1 < 128) ? (k2 >> 1) : 128;
#pragma unroll 1
        for (int j2 = jhi; j2 >= 8; j2 >>= 1) {
            int m = j2 >> 3;
            bool lo = ((tid & m) == 0);
#pragma unroll
            for (int e = 0; e < 8; e++) {
                float b = __shfl_xor_sync(0xffffffffu, rv[e], m);
                int i = 8 * tid + e;
                bool up = ((i & k2) == 0);
                rv[e] = (up == lo) ? fmaxf(rv[e], b) : fminf(rv[e], b);
            }
        }
        // register passes: j2 = 4,2,1
        int jr = (k2 >> 1 < 4) ? (k2 >> 1) : 4;
#pragma unroll 1
        for (int j2 = jr; j2 >= 1; j2 >>= 1) {
#pragma unroll
            for (int e = 0; e < 8; e++) {
                if ((e & j2) == 0) {
                    int i = 8 * tid + e;
                    bool up = ((i & k2) == 0);
                    float a = rv[e], b = rv[e | j2];
                    rv[e]      = up ? fmaxf(a, b) : fminf(a, b);
                    rv[e | j2] = up ? fminf(a, b) : fmaxf(a, b);
                }
            }
        }
    }

    // ---- softmax over sorted axis ----
    if (tid == 0) s_im[600] = rv[0];          // global max (sorted descending)
    __syncthreads();
    float mx = s_im[600];
    float ev[8], part = 0.f;
#pragma unroll
    for (int e = 0; e < 8; e++) { ev[e] = __expf(rv[e] - mx); part += ev[e]; }
#pragma unroll
    for (int o = 16; o > 0; o >>= 1) part += __shfl_xor_sync(0xffffffffu, part, o);
    if ((tid & 31) == 0) s_im[tid >> 5] = part;
    __syncthreads();
    float tot = 0.f;
#pragma unroll
    for (int i = 0; i < NT / 32; i++) tot += s_im[i];
    float invZ = 1.0f / tot;

    float* gw = g_w + (size_t)blockIdx.x * S + 8 * tid;
    float4 o0 = make_float4(ev[0] * invZ, ev[1] * invZ, ev[2] * invZ, ev[3] * invZ);
    float4 o1 = make_float4(ev[4] * invZ, ev[5] * invZ, ev[6] * invZ, ev[7] * invZ);
    *(float4*)(gw)     = o0;
    *(float4*)(gw + 4) = o1;
}

// ---------------- out[bh,i,l] = sum_j W[bh,j,i] * V[bh,j,l] ----------------
__global__ __launch_bounds__(256) void wgemm(const float* __restrict__ v, float* __restrict__ out) {
    __shared__ float Vs[D * D];
    __shared__ float Ws[D][128];
    int bh  = blockIdx.y;
    int i0  = blockIdx.x * 128;
    int tid = threadIdx.x;
    const float* vb = v + (size_t)bh * S * D;
#pragma unroll
    for (int p = 0; p < (D * D) / 256; p++) Vs[tid + p * 256] = vb[tid + p * 256];
    const float* wb = g_w + (size_t)bh * D * S + i0;
#pragma unroll
    for (int p = 0; p < (D * 128) / 256; p++) {
        int q = tid + p * 256;
        int j = q >> 7, i = q & 127;
        Ws[j][i] = wb[(size_t)j * S + i];
    }
    __syncthreads();
    int il = tid & 15, ir = tid >> 4;
    float acc[8][4];
#pragma unroll
    for (int a = 0; a < 8; a++)
#pragma unroll
        for (int b = 0; b < 4; b++) acc[a][b] = 0.f;
#pragma unroll 4
    for (int j = 0; j < D; j++) {
        float4 vl = *(const float4*)&Vs[j * D + il * 4];
#pragma unroll
        for (int a = 0; a < 8; a++) {
            float wv = Ws[j][ir * 8 + a];
            acc[a][0] += wv * vl.x;
            acc[a][1] += wv * vl.y;
            acc[a][2] += wv * vl.z;
            acc[a][3] += wv * vl.w;
        }
    }
    float* ob = out + ((size_t)bh * S + i0) * D;
#pragma unroll
    for (int a = 0; a < 8; a++) {
        float4 o = make_float4(acc[a][0], acc[a][1], acc[a][2], acc[a][3]);
        *(float4*)&ob[(size_t)(ir * 8 + a) * D + il * 4] = o;
    }
}

extern "C" void kernel_launch(void* const* d_in, const int* in_sizes, int n_in,
                              void* d_out, int out_size) {
    const float* q = (const float*)d_in[0];
    const float* k = (const float*)d_in[1];
    const float* v = (const float*)d_in[2];
    float* out = (float*)d_out;

    dim3 tb(32, 8);
    dim3 tg(S / 32, D / 32, BH);
    transpose_pack<<<tg, tb>>>(q, k);

    fft_corr_sort<<<BH * D, NT>>>();

    dim3 gg(S / 128, BH);
    wgemm<<<gg, 256>>>(v, out);
}

// round 3
// speedup vs baseline: 1.3944x; 1.1008x over previous
#include <cuda_runtime.h>
#include <math.h>

#define BH   64
#define S    4096
#define D    64
#define NT   512
#define SIDX(a) ((a) + ((a) >> 3))

// Static scratch (allocation-free rule: __device__ globals)
__device__ float2 g_x[(size_t)BH * D * S];   // packed q + i*k, layout [bh][d][s]
__device__ float  g_w[(size_t)BH * D * S];   // sorted softmax weights [bh][d][i]

// ---------------- packed f32x2 complex helpers ----------------
union f2u { float2 f; unsigned long long u; };

__device__ __forceinline__ float2 padd(float2 a, float2 b) {
    f2u A, B, R; A.f = a; B.f = b;
    asm("add.rn.f32x2 %0, %1, %2;" : "=l"(R.u) : "l"(A.u), "l"(B.u));
    return R.f;
}
// a - b  ==  fma(b, -1, a)  (packed)
__device__ __forceinline__ float2 psub(float2 a, float2 b) {
    f2u A, B, R, M; A.f = a; B.f = b; M.f = make_float2(-1.f, -1.f);
    asm("fma.rn.f32x2 %0, %1, %2, %3;" : "=l"(R.u) : "l"(B.u), "l"(M.u), "l"(A.u));
    return R.f;
}
__device__ __forceinline__ float2 cmul(float2 a, float2 b) {
    return make_float2(fmaf(a.x, b.x, -a.y * b.y), fmaf(a.x, b.y, a.y * b.x));
}
__device__ __forceinline__ float2 cconj(float2 a) { return make_float2(a.x, -a.y); }

// W_4096^e for e in [0, 4096): table of 1024 + rotation by (-i)^(e>>10)
__device__ __forceinline__ float2 twid(const float2* __restrict__ T, int e) {
    float2 t = T[e & 1023];
    int q = e >> 10;
    float2 r = t;
    if (q & 1) r = make_float2(r.y, -r.x);
    if (q & 2) r = make_float2(-r.x, -r.y);
    return r;
}

// octal-digit reversal of 12-bit index
__device__ __forceinline__ int rev8(int f) {
    return ((f & 7) << 9) | (((f >> 3) & 7) << 6) | (((f >> 6) & 7) << 3) | ((f >> 9) & 7);
}

// 8-point DFT in registers, natural-order outputs. SGN=-1 forward, +1 inverse.
template<int SGN>
__device__ __forceinline__ void dft8(float2 v[8]) {
    const float c = 0.70710678118654752f;
    float2 a0 = padd(v[0], v[4]), a4 = psub(v[0], v[4]);
    float2 a1 = padd(v[1], v[5]), a5 = psub(v[1], v[5]);
    float2 a2 = padd(v[2], v[6]), a6 = psub(v[2], v[6]);
    float2 a3 = padd(v[3], v[7]), a7 = psub(v[3], v[7]);
    a5 = cmul(a5, make_float2(c, SGN * c));
    a6 = (SGN < 0) ? make_float2(a6.y, -a6.x) : make_float2(-a6.y, a6.x);
    a7 = cmul(a7, make_float2(-c, SGN * c));
    // even group -> Y0,Y4,Y2,Y6
    float2 b0 = padd(a0, a2), b2 = psub(a0, a2);
    float2 b1 = padd(a1, a3), b3 = psub(a1, a3);
    b3 = (SGN < 0) ? make_float2(b3.y, -b3.x) : make_float2(-b3.y, b3.x);
    float2 e0 = padd(b0, b1), e1 = psub(b0, b1);
    float2 e2 = padd(b2, b3), e3 = psub(b2, b3);
    // odd group -> Y1,Y5,Y3,Y7
    float2 d0 = padd(a4, a6), d2 = psub(a4, a6);
    float2 d1 = padd(a5, a7), d3 = psub(a5, a7);
    d3 = (SGN < 0) ? make_float2(d3.y, -d3.x) : make_float2(-d3.y, d3.x);
    float2 o0 = padd(d0, d1), o1 = psub(d0, d1);
    float2 o2 = padd(d2, d3), o3 = psub(d2, d3);
    v[0] = e0; v[4] = e1; v[2] = e2; v[6] = e3;
    v[1] = o0; v[5] = o1; v[3] = o2; v[7] = o3;
}

// ---------------- transpose + pack:  [bh][s][d] -> [bh][d][s] as (q, k) float2 ----------------
__global__ void transpose_pack(const float* __restrict__ q, const float* __restrict__ k) {
    __shared__ float qt[32][33];
    __shared__ float kt[32][33];
    int bh = blockIdx.z;
    int s0 = blockIdx.x * 32;
    int d0 = blockIdx.y * 32;
    int tx = threadIdx.x, ty = threadIdx.y;
    const float* qb = q + (size_t)bh * S * D;
    const float* kb = k + (size_t)bh * S * D;
#pragma unroll
    for (int r = 0; r < 4; r++) {
        int s = s0 + ty + r * 8;
        qt[ty + r * 8][tx] = qb[(size_t)s * D + d0 + tx];
        kt[ty + r * 8][tx] = kb[(size_t)s * D + d0 + tx];
    }
    __syncthreads();
#pragma unroll
    for (int r = 0; r < 4; r++) {
        int d = d0 + ty + r * 8;
        int s = s0 + tx;
        g_x[((size_t)bh * D + d) * S + s] = make_float2(qt[tx][ty + r * 8], kt[tx][ty + r * 8]);
    }
}

// ---------------- per-series: radix-8 FFT -> cross-spectrum -> IFFT -> hybrid bitonic sort -> softmax ----------------
__global__ __launch_bounds__(NT, 2) void fft_corr_sort() {
    __shared__ float2 sx[SIDX(S - 1) + 1];   // ~36.9 KB (padded)
    __shared__ float2 s_tw[1024];            // 8 KB : W_4096^k, k=0..1023
    int tid = threadIdx.x;
    const float2* gx = g_x + (size_t)blockIdx.x * S;

    // precise twiddle table
#pragma unroll
    for (int k = tid; k < 1024; k += NT) {
        float sn, cs;
        sincospif(-(float)k / 2048.0f, &sn, &cs);
        s_tw[k] = make_float2(cs, sn);
    }

    float2 v[8];

    // ---- forward stage 0 : stride 512, p=tid (load from global) ----
#pragma unroll
    for (int r = 0; r < 8; r++) v[r] = gx[tid + 512 * r];
    __syncthreads();                       // twiddle table ready
    dft8<-1>(v);
#pragma unroll
    for (int r = 1; r < 8; r++) v[r] = cmul(v[r], twid(s_tw, tid * r));
#pragma unroll
    for (int r = 0; r < 8; r++) sx[SIDX(tid + 512 * r)] = v[r];
    __syncthreads();
    // ---- forward stage 1 : stride 64 ----
    {
        int base = (tid >> 6) << 9, p = tid & 63;
#pragma unroll
        for (int r = 0; r < 8; r++) v[r] = sx[SIDX(base + p + 64 * r)];
        dft8<-1>(v);
#pragma unroll
        for (int r = 1; r < 8; r++) v[r] = cmul(v[r], twid(s_tw, (p * r) << 3));
#pragma unroll
        for (int r = 0; r < 8; r++) sx[SIDX(base + p + 64 * r)] = v[r];
    }
    __syncthreads();
    // ---- forward stage 2 : stride 8 ----
    {
        int base = (tid >> 3) << 6, p = tid & 7;
#pragma unroll
        for (int r = 0; r < 8; r++) v[r] = sx[SIDX(base + p + 8 * r)];
        dft8<-1>(v);
#pragma unroll
        for (int r = 1; r < 8; r++) v[r] = cmul(v[r], twid(s_tw, (p * r) << 6));
#pragma unroll
        for (int r = 0; r < 8; r++) sx[SIDX(base + p + 8 * r)] = v[r];
    }
    __syncthreads();
    // ---- forward stage 3 : stride 1, no twiddle ----
    {
        int base = tid << 3;
#pragma unroll
        for (int r = 0; r < 8; r++) v[r] = sx[SIDX(base + r)];
        dft8<-1>(v);
#pragma unroll
        for (int r = 0; r < 8; r++) sx[SIDX(base + r)] = v[r];
    }
    __syncthreads();

    // ---- cross-spectrum P[f] = Q[f]*conj(K[f]) in octal-digit-reversed layout ----
    for (int f = tid; f <= 2048; f += NT) {
        int fp = (S - f) & (S - 1);
        int j  = rev8(f), jp = rev8(fp);
        float2 X  = sx[SIDX(j)];
        float2 Xp = sx[SIDX(jp)];
        float Qr = 0.5f * (X.x + Xp.x);
        float Qi = 0.5f * (X.y - Xp.y);
        float Kr = 0.5f * (X.y + Xp.y);
        float Ki = 0.5f * (Xp.x - X.x);
        float Pr = Qr * Kr + Qi * Ki;
        float Pi = Qi * Kr - Qr * Ki;
        sx[SIDX(j)]  = make_float2(Pr, Pi);
        sx[SIDX(jp)] = make_float2(Pr, -Pi);
    }
    __syncthreads();

    // ---- inverse stage 0 : stride 1 ----
    {
        int base = tid << 3;
#pragma unroll
        for (int r = 0; r < 8; r++) v[r] = sx[SIDX(base + r)];
        dft8<1>(v);
#pragma unroll
        for (int r = 0; r < 8; r++) sx[SIDX(base + r)] = v[r];
    }
    __syncthreads();
    // ---- inverse stage 1 : stride 8 ----
    {
        int base = (tid >> 3) << 6, p = tid & 7;
#pragma unroll
        for (int r = 0; r < 8; r++) v[r] = sx[SIDX(base + p + 8 * r)];
#pragma unroll
        for (int r = 1; r < 8; r++) v[r] = cmul(v[r], cconj(twid(s_tw, (p * r) << 6)));
        dft8<1>(v);
#pragma unroll
        for (int r = 0; r < 8; r++) sx[SIDX(base + p + 8 * r)] = v[r];
    }
    __syncthreads();
    // ---- inverse stage 2 : stride 64 ----
    {
        int base = (tid >> 6) << 9, p = tid & 63;
#pragma unroll
        for (int r = 0; r < 8; r++) v[r] = sx[SIDX(base + p + 64 * r)];
#pragma unroll
        for (int r = 1; r < 8; r++) v[r] = cmul(v[r], cconj(twid(s_tw, (p * r) << 3)));
        dft8<1>(v);
#pragma unroll
        for (int r = 0; r < 8; r++) sx[SIDX(base + p + 64 * r)] = v[r];
    }
    __syncthreads();
    // ---- inverse stage 3 : stride 512 ; keep only scaled real part ----
    {
        const float invN = 1.0f / (float)S;
#pragma unroll
        for (int r = 0; r < 8; r++) v[r] = sx[SIDX(tid + 512 * r)];
#pragma unroll
        for (int r = 1; r < 8; r++) v[r] = cmul(v[r], cconj(twid(s_tw, tid * r)));
        dft8<1>(v);
        __syncthreads();
        float* vals = (float*)sx;
#pragma unroll
        for (int r = 0; r < 8; r++) vals[SIDX(tid + 512 * r)] = v[r].x * invN;
    }
    __syncthreads();

    // ---- hybrid bitonic sort, descending. Thread t owns elements [8t, 8t+8). ----
    float* vals = (float*)sx;
    float rv[8];
#pragma unroll
    for (int e = 0; e < 8; e++) rv[e] = vals[SIDX(8 * tid + e)];

#pragma unroll 1
    for (int k2 = 2; k2 <= S; k2 <<= 1) {
        // smem passes: j2 >= 256 (cross-warp)
#pragma unroll 1
        for (int j2 = k2 >> 1; j2 >= 256; j2 >>= 1) {
#pragma unroll
            for (int e = 0; e < 8; e++) vals[SIDX(8 * tid + e)] = rv[e];
            __syncthreads();
#pragma unroll
            for (int e = 0; e < 8; e++) {
                int i = 8 * tid + e;
                float b = vals[SIDX(i ^ j2)];
                bool up = ((i & k2) == 0);
                bool lo = ((i & j2) == 0);
                rv[e] = (up == lo) ? fmaxf(rv[e], b) : fminf(rv[e], b);
            }
            __syncthreads();
        }
        // shfl passes: 8 <= j2 <= 128 (within-warp, no syncs)
        int jhi = (k2 >> 1 < 128) ? (k2 >> 1) : 128;
#pragma unroll 1
        for (int j2 = jhi; j2 >= 8; j2 >>= 1) {
            int m = j2 >> 3;
            bool lo = ((tid & m) == 0);
#pragma unroll
            for (int e = 0; e < 8; e++) {
                float b = __shfl_xor_sync(0xffffffffu, rv[e], m);
                int i = 8 * tid + e;
                bool up = ((i & k2) == 0);
                rv[e] = (up == lo) ? fmaxf(rv[e], b) : fminf(rv[e], b);
            }
        }
        // register passes: j2 = 4,2,1
        int jr = (k2 >> 1 < 4) ? (k2 >> 1) : 4;
#pragma unroll 1
        for (int j2 = jr; j2 >= 1; j2 >>= 1) {
#pragma unroll
            for (int e = 0; e < 8; e++) {
                if ((e & j2) == 0) {
                    int i = 8 * tid + e;
                    bool up = ((i & k2) == 0);
                    float a = rv[e], b = rv[e | j2];
                    rv[e]      = up ? fmaxf(a, b) : fminf(a, b);
                    rv[e | j2] = up ? fminf(a, b) : fmaxf(a, b);
                }
            }
        }
    }

    // ---- softmax over sorted axis (twiddle table area reused for reductions) ----
    float* red = (float*)s_tw;
    if (tid == 0) red[100] = rv[0];          // global max (sorted descending)
    __syncthreads();
    float mx = red[100];
    float ev[8], part = 0.f;
#pragma unroll
    for (int e = 0; e < 8; e++) { ev[e] = __expf(rv[e] - mx); part += ev[e]; }
#pragma unroll
    for (int o = 16; o > 0; o >>= 1) part += __shfl_xor_sync(0xffffffffu, part, o);
    if ((tid & 31) == 0) red[tid >> 5] = part;
    __syncthreads();
    float tot = 0.f;
#pragma unroll
    for (int i = 0; i < NT / 32; i++) tot += red[i];
    float invZ = 1.0f / tot;

    float* gw = g_w + (size_t)blockIdx.x * S + 8 * tid;
    float4 o0 = make_float4(ev[0] * invZ, ev[1] * invZ, ev[2] * invZ, ev[3] * invZ);
    float4 o1 = make_float4(ev[4] * invZ, ev[5] * invZ, ev[6] * invZ, ev[7] * invZ);
    *(float4*)(gw)     = o0;
    *(float4*)(gw + 4) = o1;
}

// ---------------- out[bh,i,l] = sum_j W[bh,j,i] * V[bh,j,l] ----------------
__global__ __launch_bounds__(256) void wgemm(const float* __restrict__ v, float* __restrict__ out) {
    __shared__ float Vs[D * D];
    __shared__ float Ws[D][128];
    int bh  = blockIdx.y;
    int i0  = blockIdx.x * 128;
    int tid = threadIdx.x;
    const float* vb = v + (size_t)bh * S * D;
#pragma unroll
    for (int p = 0; p < (D * D) / 256; p++) Vs[tid + p * 256] = vb[tid + p * 256];
    const float* wb = g_w + (size_t)bh * D * S + i0;
#pragma unroll
    for (int p = 0; p < (D * 128) / 256; p++) {
        int q = tid + p * 256;
        int j = q >> 7, i = q & 127;
        Ws[j][i] = wb[(size_t)j * S + i];
    }
    __syncthreads();
    int il = tid & 15, ir = tid >> 4;
    float acc[8][4];
#pragma unroll
    for (int a = 0; a < 8; a++)
#pragma unroll
        for (int b = 0; b < 4; b++) acc[a][b] = 0.f;
#pragma unroll 4
    for (int j = 0; j < D; j++) {
        float4 vl = *(const float4*)&Vs[j * D + il * 4];
#pragma unroll
        for (int a = 0; a < 8; a++) {
            float wv = Ws[j][ir * 8 + a];
            acc[a][0] += wv * vl.x;
            acc[a][1] += wv * vl.y;
            acc[a][2] += wv * vl.z;
            acc[a][3] += wv * vl.w;
        }
    }
    float* ob = out + ((size_t)bh * S + i0) * D;
#pragma unroll
    for (int a = 0; a < 8; a++) {
        float4 o = make_float4(acc[a][0], acc[a][1], acc[a][2], acc[a][3]);
        *(float4*)&ob[(size_t)(ir * 8 + a) * D + il * 4] = o;
    }
}

extern "C" void kernel_launch(void* const* d_in, const int* in_sizes, int n_in,
                              void* d_out, int out_size) {
    const float* q = (const float*)d_in[0];
    const float* k = (const float*)d_in[1];
    const float* v = (const float*)d_in[2];
    float* out = (float*)d_out;

    dim3 tb(32, 8);
    dim3 tg(S / 32, D / 32, BH);
    transpose_pack<<<tg, tb>>>(q, k);

    fft_corr_sort<<<BH * D, NT>>>();

    dim3 gg(S / 128, BH);
    wgemm<<<gg, 256>>>(v, out);
}

// round 4
// speedup vs baseline: 2.0947x; 1.5022x over previous
#include <cuda_runtime.h>
#include <math.h>
#include <cub/block/block_radix_sort.cuh>

#define BH   64
#define S    4096
#define D    64
#define NT   512
#define SIDX(a) ((a) + ((a) >> 3))

// Static scratch (allocation-free rule: __device__ globals)
__device__ float2 g_x[(size_t)BH * D * S];   // packed q + i*k, layout [bh][d][s]
__device__ float  g_w[(size_t)BH * D * S];   // sorted softmax weights [bh][d][i]

// ---------------- packed f32x2 complex helpers ----------------
union f2u { float2 f; unsigned long long u; };

__device__ __forceinline__ float2 padd(float2 a, float2 b) {
    f2u A, B, R; A.f = a; B.f = b;
    asm("add.rn.f32x2 %0, %1, %2;" : "=l"(R.u) : "l"(A.u), "l"(B.u));
    return R.f;
}
// a - b  ==  fma(b, -1, a)  (packed)
__device__ __forceinline__ float2 psub(float2 a, float2 b) {
    f2u A, B, R, M; A.f = a; B.f = b; M.f = make_float2(-1.f, -1.f);
    asm("fma.rn.f32x2 %0, %1, %2, %3;" : "=l"(R.u) : "l"(B.u), "l"(M.u), "l"(A.u));
    return R.f;
}
__device__ __forceinline__ float2 cmul(float2 a, float2 b) {
    return make_float2(fmaf(a.x, b.x, -a.y * b.y), fmaf(a.x, b.y, a.y * b.x));
}
__device__ __forceinline__ float2 cconj(float2 a) { return make_float2(a.x, -a.y); }

// W_4096^e for e in [0, 4096): table of 1024 + rotation by (-i)^(e>>10)
__device__ __forceinline__ float2 twid(const float2* __restrict__ T, int e) {
    float2 t = T[e & 1023];
    int q = e >> 10;
    float2 r = t;
    if (q & 1) r = make_float2(r.y, -r.x);
    if (q & 2) r = make_float2(-r.x, -r.y);
    return r;
}

// octal-digit reversal of 12-bit index
__device__ __forceinline__ int rev8(int f) {
    return ((f & 7) << 9) | (((f >> 3) & 7) << 6) | (((f >> 6) & 7) << 3) | ((f >> 9) & 7);
}

// 8-point DFT in registers, natural-order outputs. SGN=-1 forward, +1 inverse.
template<int SGN>
__device__ __forceinline__ void dft8(float2 v[8]) {
    const float c = 0.70710678118654752f;
    float2 a0 = padd(v[0], v[4]), a4 = psub(v[0], v[4]);
    float2 a1 = padd(v[1], v[5]), a5 = psub(v[1], v[5]);
    float2 a2 = padd(v[2], v[6]), a6 = psub(v[2], v[6]);
    float2 a3 = padd(v[3], v[7]), a7 = psub(v[3], v[7]);
    a5 = cmul(a5, make_float2(c, SGN * c));
    a6 = (SGN < 0) ? make_float2(a6.y, -a6.x) : make_float2(-a6.y, a6.x);
    a7 = cmul(a7, make_float2(-c, SGN * c));
    float2 b0 = padd(a0, a2), b2 = psub(a0, a2);
    float2 b1 = padd(a1, a3), b3 = psub(a1, a3);
    b3 = (SGN < 0) ? make_float2(b3.y, -b3.x) : make_float2(-b3.y, b3.x);
    float2 e0 = padd(b0, b1), e1 = psub(b0, b1);
    float2 e2 = padd(b2, b3), e3 = psub(b2, b3);
    float2 d0 = padd(a4, a6), d2 = psub(a4, a6);
    float2 d1 = padd(a5, a7), d3 = psub(a5, a7);
    d3 = (SGN < 0) ? make_float2(d3.y, -d3.x) : make_float2(-d3.y, d3.x);
    float2 o0 = padd(d0, d1), o1 = psub(d0, d1);
    float2 o2 = padd(d2, d3), o3 = psub(d2, d3);
    v[0] = e0; v[4] = e1; v[2] = e2; v[6] = e3;
    v[1] = o0; v[5] = o1; v[3] = o2; v[7] = o3;
}

// ---------------- transpose + pack:  [bh][s][d] -> [bh][d][s] as (q, k) float2 ----------------
__global__ void transpose_pack(const float* __restrict__ q, const float* __restrict__ k) {
    __shared__ float qt[32][33];
    __shared__ float kt[32][33];
    int bh = blockIdx.z;
    int s0 = blockIdx.x * 32;
    int d0 = blockIdx.y * 32;
    int tx = threadIdx.x, ty = threadIdx.y;
    const float* qb = q + (size_t)bh * S * D;
    const float* kb = k + (size_t)bh * S * D;
#pragma unroll
    for (int r = 0; r < 4; r++) {
        int s = s0 + ty + r * 8;
        qt[ty + r * 8][tx] = qb[(size_t)s * D + d0 + tx];
        kt[ty + r * 8][tx] = kb[(size_t)s * D + d0 + tx];
    }
    __syncthreads();
#pragma unroll
    for (int r = 0; r < 4; r++) {
        int d = d0 + ty + r * 8;
        int s = s0 + tx;
        g_x[((size_t)bh * D + d) * S + s] = make_float2(qt[tx][ty + r * 8], kt[tx][ty + r * 8]);
    }
}

// ---------------- per-series: radix-8 FFT -> cross-spectrum -> IFFT -> radix sort -> softmax ----------------
using BlockRadixSortT = cub::BlockRadixSort<float, NT, 8, cub::NullType, 4>;

__global__ __launch_bounds__(NT, 2) void fft_corr_sort() {
    __shared__ union SmemU {
        float2 sx[SIDX(S - 1) + 1];                  // ~36.9 KB (padded)
        typename BlockRadixSortT::TempStorage sort;  // cub radix sort scratch
    } u;
    static_assert(sizeof(typename BlockRadixSortT::TempStorage) <= sizeof(float2) * (SIDX(S - 1) + 1),
                  "cub temp storage must fit in FFT buffer");
    __shared__ float2 s_tw[1024];            // 8 KB : W_4096^k, k=0..1023
    float2* sx = u.sx;
    int tid = threadIdx.x;
    const float2* gx = g_x + (size_t)blockIdx.x * S;

    // precise twiddle table
#pragma unroll
    for (int k = tid; k < 1024; k += NT) {
        float sn, cs;
        sincospif(-(float)k / 2048.0f, &sn, &cs);
        s_tw[k] = make_float2(cs, sn);
    }

    float2 v[8];

    // ---- forward stage 0 : stride 512, p=tid (load from global) ----
#pragma unroll
    for (int r = 0; r < 8; r++) v[r] = gx[tid + 512 * r];
    __syncthreads();                       // twiddle table ready
    dft8<-1>(v);
#pragma unroll
    for (int r = 1; r < 8; r++) v[r] = cmul(v[r], twid(s_tw, tid * r));
#pragma unroll
    for (int r = 0; r < 8; r++) sx[SIDX(tid + 512 * r)] = v[r];
    __syncthreads();
    // ---- forward stage 1 : stride 64 ----
    {
        int base = (tid >> 6) << 9, p = tid & 63;
#pragma unroll
        for (int r = 0; r < 8; r++) v[r] = sx[SIDX(base + p + 64 * r)];
        dft8<-1>(v);
#pragma unroll
        for (int r = 1; r < 8; r++) v[r] = cmul(v[r], twid(s_tw, (p * r) << 3));
#pragma unroll
        for (int r = 0; r < 8; r++) sx[SIDX(base + p + 64 * r)] = v[r];
    }
    __syncthreads();
    // ---- forward stage 2 : stride 8 ----
    {
        int base = (tid >> 3) << 6, p = tid & 7;
#pragma unroll
        for (int r = 0; r < 8; r++) v[r] = sx[SIDX(base + p + 8 * r)];
        dft8<-1>(v);
#pragma unroll
        for (int r = 1; r < 8; r++) v[r] = cmul(v[r], twid(s_tw, (p * r) << 6));
#pragma unroll
        for (int r = 0; r < 8; r++) sx[SIDX(base + p + 8 * r)] = v[r];
    }
    __syncthreads();
    // ---- forward stage 3 : stride 1, no twiddle ----
    {
        int base = tid << 3;
#pragma unroll
        for (int r = 0; r < 8; r++) v[r] = sx[SIDX(base + r)];
        dft8<-1>(v);
#pragma unroll
        for (int r = 0; r < 8; r++) sx[SIDX(base + r)] = v[r];
    }
    __syncthreads();

    // ---- cross-spectrum P[f] = Q[f]*conj(K[f]) in octal-digit-reversed layout ----
    for (int f = tid; f <= 2048; f += NT) {
        int fp = (S - f) & (S - 1);
        int j  = rev8(f), jp = rev8(fp);
        float2 X  = sx[SIDX(j)];
        float2 Xp = sx[SIDX(jp)];
        float Qr = 0.5f * (X.x + Xp.x);
        float Qi = 0.5f * (X.y - Xp.y);
        float Kr = 0.5f * (X.y + Xp.y);
        float Ki = 0.5f * (Xp.x - X.x);
        float Pr = Qr * Kr + Qi * Ki;
        float Pi = Qi * Kr - Qr * Ki;
        sx[SIDX(j)]  = make_float2(Pr, Pi);
        sx[SIDX(jp)] = make_float2(Pr, -Pi);
    }
    __syncthreads();

    // ---- inverse stage 0 : stride 1 ----
    {
        int base = tid << 3;
#pragma unroll
        for (int r = 0; r < 8; r++) v[r] = sx[SIDX(base + r)];
        dft8<1>(v);
#pragma unroll
        for (int r = 0; r < 8; r++) sx[SIDX(base + r)] = v[r];
    }
    __syncthreads();
    // ---- inverse stage 1 : stride 8 ----
    {
        int base = (tid >> 3) << 6, p = tid & 7;
#pragma unroll
        for (int r = 0; r < 8; r++) v[r] = sx[SIDX(base + p + 8 * r)];
#pragma unroll
        for (int r = 1; r < 8; r++) v[r] = cmul(v[r], cconj(twid(s_tw, (p * r) << 6)));
        dft8<1>(v);
#pragma unroll
        for (int r = 0; r < 8; r++) sx[SIDX(base + p + 8 * r)] = v[r];
    }
    __syncthreads();
    // ---- inverse stage 2 : stride 64 ----
    {
        int base = (tid >> 6) << 9, p = tid & 63;
#pragma unroll
        for (int r = 0; r < 8; r++) v[r] = sx[SIDX(base + p + 64 * r)];
#pragma unroll
        for (int r = 1; r < 8; r++) v[r] = cmul(v[r], cconj(twid(s_tw, (p * r) << 3)));
        dft8<1>(v);
#pragma unroll
        for (int r = 0; r < 8; r++) sx[SIDX(base + p + 64 * r)] = v[r];
    }
    __syncthreads();
    // ---- inverse stage 3 : stride 512 ; keep only scaled real part ----
    {
        const float invN = 1.0f / (float)S;
#pragma unroll
        for (int r = 0; r < 8; r++) v[r] = sx[SIDX(tid + 512 * r)];
#pragma unroll
        for (int r = 1; r < 8; r++) v[r] = cmul(v[r], cconj(twid(s_tw, tid * r)));
        dft8<1>(v);
        __syncthreads();
        float* vals = (float*)sx;
#pragma unroll
        for (int r = 0; r < 8; r++) vals[SIDX(tid + 512 * r)] = v[r].x * invN;
    }
    __syncthreads();

    // ---- gather per-thread run, then block radix sort (descending) ----
    float rv[8];
    {
        float* vals = (float*)sx;
#pragma unroll
        for (int e = 0; e < 8; e++) rv[e] = vals[SIDX(8 * tid + e)];
    }
    __syncthreads();                        // all reads done before cub reuses the buffer
    BlockRadixSortT(u.sort).SortDescending(rv);
    __syncthreads();                        // cub storage quiesced

    // ---- softmax over sorted axis (twiddle table area reused for reductions) ----
    float* red = (float*)s_tw;
    if (tid == 0) red[100] = rv[0];          // global max (sorted descending)
    __syncthreads();
    float mx = red[100];
    float ev[8], part = 0.f;
#pragma unroll
    for (int e = 0; e < 8; e++) { ev[e] = __expf(rv[e] - mx); part += ev[e]; }
#pragma unroll
    for (int o = 16; o > 0; o >>= 1) part += __shfl_xor_sync(0xffffffffu, part, o);
    if ((tid & 31) == 0) red[tid >> 5] = part;
    __syncthreads();
    float tot = 0.f;
#pragma unroll
    for (int i = 0; i < NT / 32; i++) tot += red[i];
    float invZ = 1.0f / tot;

    float* gw = g_w + (size_t)blockIdx.x * S + 8 * tid;
    float4 o0 = make_float4(ev[0] * invZ, ev[1] * invZ, ev[2] * invZ, ev[3] * invZ);
    float4 o1 = make_float4(ev[4] * invZ, ev[5] * invZ, ev[6] * invZ, ev[7] * invZ);
    *(float4*)(gw)     = o0;
    *(float4*)(gw + 4) = o1;
}

// ---------------- out[bh,i,l] = sum_j W[bh,j,i] * V[bh,j,l] ----------------
__global__ __launch_bounds__(256) void wgemm(const float* __restrict__ v, float* __restrict__ out) {
    __shared__ float Vs[D * D];
    __shared__ float Ws[D][128];
    int bh  = blockIdx.y;
    int i0  = blockIdx.x * 128;
    int tid = threadIdx.x;
    const float* vb = v + (size_t)bh * S * D;
#pragma unroll
    for (int p = 0; p < (D * D) / 256; p++) Vs[tid + p * 256] = vb[tid + p * 256];
    const float* wb = g_w + (size_t)bh * D * S + i0;
#pragma unroll
    for (int p = 0; p < (D * 128) / 256; p++) {
        int q = tid + p * 256;
        int j = q >> 7, i = q & 127;
        Ws[j][i] = wb[(size_t)j * S + i];
    }
    __syncthreads();
    int il = tid & 15, ir = tid >> 4;
    float acc[8][4];
#pragma unroll
    for (int a = 0; a < 8; a++)
#pragma unroll
        for (int b = 0; b < 4; b++) acc[a][b] = 0.f;
#pragma unroll 4
    for (int j = 0; j < D; j++) {
        float4 vl = *(const float4*)&Vs[j * D + il * 4];
#pragma unroll
        for (int a = 0; a < 8; a++) {
            float wv = Ws[j][ir * 8 + a];
            acc[a][0] += wv * vl.x;
            acc[a][1] += wv * vl.y;
            acc[a][2] += wv * vl.z;
            acc[a][3] += wv * vl.w;
        }
    }
    float* ob = out + ((size_t)bh * S + i0) * D;
#pragma unroll
    for (int a = 0; a < 8; a++) {
        float4 o = make_float4(acc[a][0], acc[a][1], acc[a][2], acc[a][3]);
        *(float4*)&ob[(size_t)(ir * 8 + a) * D + il * 4] = o;
    }
}

extern "C" void kernel_launch(void* const* d_in, const int* in_sizes, int n_in,
                              void* d_out, int out_size) {
    const float* q = (const float*)d_in[0];
    const float* k = (const float*)d_in[1];
    const float* v = (const float*)d_in[2];
    float* out = (float*)d_out;

    dim3 tb(32, 8);
    dim3 tg(S / 32, D / 32, BH);
    transpose_pack<<<tg, tb>>>(q, k);

    fft_corr_sort<<<BH * D, NT>>>();

    dim3 gg(S / 128, BH);
    wgemm<<<gg, 256>>>(v, out);
}